// round 8
// baseline (speedup 1.0000x reference)
#include <cuda_runtime.h>
#include <cuda_fp16.h>

#define IMG_H 1024
#define IMG_W 1024
#define N_PLANES 24   // B*C = 8*3
#define RES_SCALE 0.2f

__device__ __forceinline__ __half2 h2mn(__half2 a, __half2 b) { return __hmin2(a, b); }
__device__ __forceinline__ __half2 h2mx(__half2 a, __half2 b) { return __hmax2(a, b); }

// Load one image row segment (cols c0-1 .. c0+4) into v[6] (fp32).
// Halo via intra-warp shuffle; lanes 0/31 use predicated scalar loads.
__device__ __forceinline__ void load_row(const float* __restrict__ row, bool valid,
                                         int c0, int lane, float* v) {
    const float4 z4 = make_float4(0.f, 0.f, 0.f, 0.f);
    float4 q = valid ? *(const float4*)(row + c0) : z4;
    const bool pL = (lane == 0);
    const bool pR = (lane == 31);
    float hl = (pL & (c0 > 0) & valid)         ? row[c0 - 1] : 0.f;
    float hr = (pR & (c0 + 4 < IMG_W) & valid) ? row[c0 + 4] : 0.f;
    const unsigned fm = 0xffffffffu;
    float sl = __shfl_up_sync(fm, q.w, 1);
    float sr = __shfl_down_sync(fm, q.x, 1);
    v[0] = pL ? hl : sl;
    v[1] = q.x; v[2] = q.y; v[3] = q.z; v[4] = q.w;
    v[5] = pR ? hr : sr;
}

// Packed column sort: windows (x-half, y-half) share pre-sorted vertical pair (s,t).
__device__ __forceinline__ void colsort_pk(const __half2* s, const __half2* t, const __half2* o,
                                           __half2* lo, __half2* mi, __half2* hi) {
#pragma unroll
    for (int j = 0; j < 6; j++) {
        lo[j] = h2mn(o[j], s[j]);
        hi[j] = h2mx(o[j], t[j]);
        mi[j] = h2mx(s[j], h2mn(o[j], t[j]));
    }
}

// Packed horizontal combine for 2 window-rows; residual in fp32 with exact x;
// streams 2 output rows (centers xr0 -> ob0 and xr1 -> ob1).
__device__ __forceinline__ void combine_pk(const __half2* lo, const __half2* mi, const __half2* hi,
                                           const float* xr0, const float* xr1,
                                           float* __restrict__ ob0, float* __restrict__ ob1) {
    float r0[4], r1[4];
#pragma unroll
    for (int pi = 0; pi < 2; pi++) {
        const int i = 2 * pi + 1;                 // shared pair (i, i+1)
        const __half2 pmx = h2mx(lo[i], lo[i + 1]);
        const __half2 pmn = h2mn(hi[i], hi[i + 1]);
        const __half2 psn = h2mn(mi[i], mi[i + 1]);
        const __half2 psx = h2mx(mi[i], mi[i + 1]);
        {   // window i-1 : pair + column i-1
            const __half2 M  = h2mx(lo[i - 1], pmx);
            const __half2 N  = h2mn(hi[i - 1], pmn);
            const __half2 md = h2mx(psn, h2mn(psx, mi[i - 1]));
            const __half2 mn = h2mn(M, md);
            const __half2 mx = h2mx(M, md);
            const __half2 m  = h2mx(mn, h2mn(mx, N));
            const float m0 = __low2float(m), m1 = __high2float(m);
            r0[i - 1] = xr0[i] + RES_SCALE * (m0 - xr0[i]);
            r1[i - 1] = xr1[i] + RES_SCALE * (m1 - xr1[i]);
        }
        {   // window i : pair + column i+2
            const __half2 M  = h2mx(pmx, lo[i + 2]);
            const __half2 N  = h2mn(pmn, hi[i + 2]);
            const __half2 md = h2mx(psn, h2mn(psx, mi[i + 2]));
            const __half2 mn = h2mn(M, md);
            const __half2 mx = h2mx(M, md);
            const __half2 m  = h2mx(mn, h2mn(mx, N));
            const float m0 = __low2float(m), m1 = __high2float(m);
            r0[i] = xr0[i + 1] + RES_SCALE * (m0 - xr0[i + 1]);
            r1[i] = xr1[i + 1] + RES_SCALE * (m1 - xr1[i + 1]);
        }
    }
    __stcs((float4*)(ob0), make_float4(r0[0], r0[1], r0[2], r0[3]));
    __stcs((float4*)(ob1), make_float4(r1[0], r1[1], r1[2], r1[3]));
}

__global__ __launch_bounds__(256, 4)
void MedianBlur_30966714204228_kernel(const float* __restrict__ x,
                                      float* __restrict__ out) {
    const int r     = blockIdx.x << 2;   // top output row of the quad
    const int plane = blockIdx.y;        // 0..23
    const int tid   = threadIdx.x;       // 0..255
    const int lane  = tid & 31;
    const int c0    = tid << 2;          // 4 pixels per thread per row

    const float* p    = x + (size_t)plane * (IMG_H * IMG_W);
    const float* rowB = p + (size_t)r * IMG_W;
    const bool hasA = (r > 0);
    const bool hasF = (r + 4 < IMG_H);

    // 6 input rows (fp32): A=r-1 .. F=r+4
    float A[6], B[6], C[6], D[6], E[6], F[6];
    load_row(rowB - IMG_W,     hasA, c0, lane, A);
    load_row(rowB,             true, c0, lane, B);
    load_row(rowB + IMG_W,     true, c0, lane, C);
    load_row(rowB + 2 * IMG_W, true, c0, lane, D);
    load_row(rowB + 3 * IMG_W, true, c0, lane, E);
    load_row(rowB + 4 * IMG_W, hasF, c0, lane, F);

    // Pack: x-half serves window-rows (B,C), y-half serves (D,E).
    //   u=(B,D), v=(C,E)  -> shared vertical pair sort for ALL 4 windows
    __half2 u[6], v[6], op_[6], oq[6];
#pragma unroll
    for (int j = 0; j < 6; j++) {
        u[j]   = __floats2half2_rn(B[j], D[j]);
        v[j]   = __floats2half2_rn(C[j], E[j]);
        op_[j] = __floats2half2_rn(A[j], C[j]);   // outer rows of windows (B,D)
        oq[j]  = __floats2half2_rn(D[j], F[j]);   // outer rows of windows (C,E)
    }
    __half2 s[6], t[6];
#pragma unroll
    for (int j = 0; j < 6; j++) {
        s[j] = h2mn(u[j], v[j]);
        t[j] = h2mx(u[j], v[j]);
    }

    float* ob = out + (size_t)plane * (IMG_H * IMG_W) + (size_t)r * IMG_W + c0;
    __half2 lo[6], mi[6], hi[6];

    // windows at rows B (out r) and D (out r+2)
    colsort_pk(s, t, op_, lo, mi, hi);
    combine_pk(lo, mi, hi, B, D, ob, ob + 2 * IMG_W);

    // windows at rows C (out r+1) and E (out r+3)
    colsort_pk(s, t, oq, lo, mi, hi);
    combine_pk(lo, mi, hi, C, E, ob + IMG_W, ob + 3 * IMG_W);
}

extern "C" void kernel_launch(void* const* d_in, const int* in_sizes, int n_in,
                              void* d_out, int out_size) {
    const float* x = (const float*)d_in[0];
    float* o = (float*)d_out;
    dim3 grid(IMG_H / 4, N_PLANES);
    MedianBlur_30966714204228_kernel<<<grid, 256>>>(x, o);
}